// round 1
// baseline (speedup 1.0000x reference)
#include <cuda_runtime.h>
#include <stdint.h>

#define ROW_N   2048
#define K_SEL   1024
#define NTHREADS 256

__device__ __forceinline__ uint32_t f2u_ord(uint32_t b) {
    // order-preserving transform: float bits -> ascending uint
    return (b & 0x80000000u) ? ~b : (b | 0x80000000u);
}
__device__ __forceinline__ float u2f_ord(uint32_t u) {
    uint32_t b = (u & 0x80000000u) ? (u ^ 0x80000000u) : ~u;
    return __uint_as_float(b);
}

__global__ __launch_bounds__(NTHREADS) void kta_kernel(const float* __restrict__ in,
                                                       float* __restrict__ out) {
    __shared__ uint32_t s_u[ROW_N];      // transformed row
    __shared__ uint32_t s_hist[256];     // radix histogram
    __shared__ uint32_t s_woff[8];       // per-warp scan offsets
    __shared__ uint32_t s_sel[2];        // selected digit, exclusive count

    const int t    = threadIdx.x;
    const int lane = t & 31;
    const int wid  = t >> 5;
    const size_t row_base = (size_t)blockIdx.x * ROW_N;

    const float4* in4  = (const float4*)(in  + row_base);
    float4*       out4 = (float4*)(out + row_base);

    // ---- load + transform: 2 x float4 per thread, coalesced ----
#pragma unroll
    for (int v = 0; v < 2; v++) {
        int i = t + v * NTHREADS;            // float4 index 0..511
        float4 f = in4[i];
        uint32_t u0 = f2u_ord(__float_as_uint(f.x));
        uint32_t u1 = f2u_ord(__float_as_uint(f.y));
        uint32_t u2 = f2u_ord(__float_as_uint(f.z));
        uint32_t u3 = f2u_ord(__float_as_uint(f.w));
        uint4* su4 = (uint4*)s_u;
        su4[i] = make_uint4(u0, u1, u2, u3);
    }

    // ---- 4-pass radix select for k-th smallest ----
    uint32_t prefix = 0;
    uint32_t krem   = K_SEL;

#pragma unroll
    for (int pass = 0; pass < 4; pass++) {
        const int shift = 24 - 8 * pass;
        const uint32_t hi_mask = (pass == 0) ? 0u : (0xFFFFFFFFu << (shift + 8));

        s_hist[t] = 0;
        __syncthreads();

        // histogram of matching elements (stride-256: conflict-free LDS)
        for (int e = t; e < ROW_N; e += NTHREADS) {
            uint32_t u = s_u[e];
            if ((u & hi_mask) == prefix)
                atomicAdd(&s_hist[(u >> shift) & 255u], 1u);
        }
        __syncthreads();

        // inclusive prefix scan over 256 bins: warp shuffle + cross-warp fixup
        uint32_t cnt = s_hist[t];
        uint32_t inc = cnt;
#pragma unroll
        for (int o = 1; o < 32; o <<= 1) {
            uint32_t v = __shfl_up_sync(0xFFFFFFFFu, inc, o);
            if (lane >= o) inc += v;
        }
        if (lane == 31) s_woff[wid] = inc;
        __syncthreads();
        if (t == 0) {
            uint32_t run = 0;
#pragma unroll
            for (int w = 0; w < 8; w++) { uint32_t x = s_woff[w]; s_woff[w] = run; run += x; }
        }
        __syncthreads();
        inc += s_woff[wid];
        uint32_t exc = inc - cnt;

        if (exc < krem && krem <= inc) {   // exactly one thread true
            s_sel[0] = (uint32_t)t;
            s_sel[1] = exc;
        }
        __syncthreads();

        prefix |= s_sel[0] << shift;
        krem   -= s_sel[1];
    }

    const uint32_t T = prefix;  // k-th smallest transformed value

    // ---- output: zero everything <= T ----
#pragma unroll
    for (int v = 0; v < 2; v++) {
        int i = t + v * NTHREADS;
        uint4 u4 = ((uint4*)s_u)[i];
        float4 o;
        o.x = (u4.x <= T) ? 0.0f : u2f_ord(u4.x);
        o.y = (u4.y <= T) ? 0.0f : u2f_ord(u4.y);
        o.z = (u4.z <= T) ? 0.0f : u2f_ord(u4.z);
        o.w = (u4.w <= T) ? 0.0f : u2f_ord(u4.w);
        out4[i] = o;
    }
}

extern "C" void kernel_launch(void* const* d_in, const int* in_sizes, int n_in,
                              void* d_out, int out_size) {
    const float* in = (const float*)d_in[0];
    float* out = (float*)d_out;
    int rows = in_sizes[0] / ROW_N;   // 16*2048*2048 / 2048 = 32768
    kta_kernel<<<rows, NTHREADS>>>(in, out);
}